// round 15
// baseline (speedup 1.0000x reference)
#include <cuda_runtime.h>
#include <math.h>

#define BS     8
#define NROT   60
#define NPTS   500
#define NBR    (BS * NROT)      // 480
#define HW     6400
#define NG     (NBR * NPTS)     // 240000
#define GCH    444              // chamfer blocks: exactly 3 per SM
#define TPB    288              // 9 warps
#define NWP    (TPB / 32)
#define CHUNK  5
#define BPB    30000            // g per batch (60*500)

// 240000 = 444*540 + 240  ->  first 240 blocks have 541, rest 540
__device__ __forceinline__ int g_start(int k) { return 540 * k + (k < 240 ? k : 240); }
__device__ __forceinline__ int block_of(int g) {
    return (g < 541 * 240) ? g / 541 : (g - 240) / 540;
}

// Scratch (allocation-free: __device__ globals)
__device__ float g_symp[GCH][3];   // per-block partials for up to 3 br segments
__device__ float g_nsp[GCH][3];
__device__ float g_scal[2];        // [0]=loss_reg, [1]=loss_t
__device__ unsigned int g_cnt;

__device__ __forceinline__ void rot_point(
    const float* __restrict__ pred_r, const float* __restrict__ model_points,
    int br, int b, int n, float& px, float& py, float& pz, float& a2)
{
    const float* q = pred_r + (size_t)br * 4;
    float w = q[0], x = q[1], y = q[2], z = q[3];
    float r00 = 1.f - 2.f*(y*y + z*z);
    float r01 = 2.f*x*y - 2.f*w*z;
    float r02 = 2.f*w*y + 2.f*x*z;
    float r10 = 2.f*x*y + 2.f*z*w;
    float r11 = 1.f - 2.f*(x*x + z*z);
    float r12 = -2.f*w*x + 2.f*y*z;
    float r20 = -2.f*w*y + 2.f*x*z;
    float r21 = 2.f*w*x + 2.f*y*z;
    float r22 = 1.f - 2.f*(x*x + y*y);
    const float* mp = model_points + (size_t)b * NPTS * 3 + (size_t)n * 3;
    float mx = mp[0], my = mp[1], mz = mp[2];
    px = r00*mx + r01*my + r02*mz;
    py = r10*mx + r11*my + r12*mz;
    pz = r20*mx + r21*my + r22*mz;
    a2 = px*px + py*py + pz*pz;
}

__global__ __launch_bounds__(TPB, 3) void fused_kernel(
    const float* __restrict__ pred_t,
    const float* __restrict__ pred_r,
    const float* __restrict__ pred_c,
    const float* __restrict__ target_r,
    const float* __restrict__ target_t,
    const float* __restrict__ model_points,
    const int*   __restrict__ choose,
    const int*   __restrict__ symmetric,
    const float* __restrict__ diameters,
    const float* __restrict__ rot_anchors,
    float*       __restrict__ out)
{
    __shared__ float4 tg[2][NPTS];       // up to two batch tiles
    __shared__ float  red6[NWP][6];
    __shared__ float  red1[NWP];
    __shared__ int    s_last;

    const int tid  = threadIdx.x;
    const int lane = tid & 31;
    const int wid  = tid >> 5;
    const int blk  = blockIdx.x;

    if (blk < GCH) {
        // ============ chamfer block: g in [gS, gE) ============
        const int gS   = g_start(blk);
        const int gE   = g_start(blk + 1);
        const int npts = gE - gS;                 // 540 or 541
        const int b0   = gS / BPB;
        const int bL   = (gE - 1) / BPB;
        const int br0  = gS / NPTS;

        // coalesced float4 tile prologue (batch b0; batch bL if straddling)
        if (tid < 125) {
            const float4* tp4 = reinterpret_cast<const float4*>(target_r + (size_t)b0 * NPTS * 3);
            float4 f0 = tp4[3*tid], f1 = tp4[3*tid+1], f2 = tp4[3*tid+2];
            tg[0][4*tid+0] = make_float4(-2.f*f0.x, -2.f*f0.y, -2.f*f0.z, f0.x*f0.x+f0.y*f0.y+f0.z*f0.z);
            tg[0][4*tid+1] = make_float4(-2.f*f0.w, -2.f*f1.x, -2.f*f1.y, f0.w*f0.w+f1.x*f1.x+f1.y*f1.y);
            tg[0][4*tid+2] = make_float4(-2.f*f1.z, -2.f*f1.w, -2.f*f2.x, f1.z*f1.z+f1.w*f1.w+f2.x*f2.x);
            tg[0][4*tid+3] = make_float4(-2.f*f2.y, -2.f*f2.z, -2.f*f2.w, f2.y*f2.y+f2.z*f2.z+f2.w*f2.w);
        } else if (bL != b0 && tid >= 160 && tid < 285) {
            int t = tid - 160;
            const float4* tp4 = reinterpret_cast<const float4*>(target_r + (size_t)bL * NPTS * 3);
            float4 f0 = tp4[3*t], f1 = tp4[3*t+1], f2 = tp4[3*t+2];
            tg[1][4*t+0] = make_float4(-2.f*f0.x, -2.f*f0.y, -2.f*f0.z, f0.x*f0.x+f0.y*f0.y+f0.z*f0.z);
            tg[1][4*t+1] = make_float4(-2.f*f0.w, -2.f*f1.x, -2.f*f1.y, f0.w*f0.w+f1.x*f1.x+f1.y*f1.y);
            tg[1][4*t+2] = make_float4(-2.f*f1.z, -2.f*f1.w, -2.f*f2.x, f1.z*f1.z+f1.w*f1.w+f2.x*f2.x);
            tg[1][4*t+3] = make_float4(-2.f*f2.y, -2.f*f2.z, -2.f*f2.w, f2.y*f2.y+f2.z*f2.z+f2.w*f2.w);
        }

        // per-point setup (2 points per thread)
        int   gi[2], bri[2], ni[2], bi[2];
        bool  val[2];
        float px[2], py[2], pz[2], a2[2];
        #pragma unroll
        for (int i = 0; i < 2; i++) {
            int l = tid + TPB * i;
            val[i] = (l < npts);
            int g = val[i] ? (gS + l) : gS;
            gi[i] = g;
            bri[i] = g / NPTS;
            ni[i]  = g - bri[i] * NPTS;
            bi[i]  = g / BPB;
            rot_point(pred_r, model_points, bri[i], bi[i], ni[i],
                      px[i], py[i], pz[i], a2[i]);
        }
        __syncthreads();

        const float INF = 3.4e38f;
        float mnA[2] = {INF, INF};
        float mnB[2] = {INF, INF};

        if (b0 == bL) {
            // common path: single tile, warp-uniform broadcast loads
            for (int j0 = 0; j0 < NPTS; j0 += CHUNK) {
                float4 T[CHUNK];
                #pragma unroll
                for (int k = 0; k < CHUNK; k++) T[k] = tg[0][j0 + k];
                #pragma unroll
                for (int k = 0; k < CHUNK; k++) {
                    #pragma unroll
                    for (int i = 0; i < 2; i++) {
                        float s = fmaf(px[i], T[k].x,
                                  fmaf(py[i], T[k].y,
                                  fmaf(pz[i], T[k].z, T[k].w)));
                        if (k & 1) mnB[i] = fminf(mnB[i], s);
                        else       mnA[i] = fminf(mnA[i], s);
                    }
                }
            }
        } else {
            // straddle path (<=7 blocks grid-wide): per-point tile pointer
            const float4* T0 = tg[bi[0] - b0];
            const float4* T1 = tg[bi[1] - b0];
            for (int j = 0; j < NPTS; j++) {
                float4 Ta = T0[j], Tb = T1[j];
                float s0 = fmaf(px[0], Ta.x, fmaf(py[0], Ta.y, fmaf(pz[0], Ta.z, Ta.w)));
                float s1 = fmaf(px[1], Tb.x, fmaf(py[1], Tb.y, fmaf(pz[1], Tb.z, Tb.w)));
                if (j & 1) { mnB[0] = fminf(mnB[0], s0); mnB[1] = fminf(mnB[1], s1); }
                else       { mnA[0] = fminf(mnA[0], s0); mnA[1] = fminf(mnA[1], s1); }
            }
        }

        // epilogue + 3-way segmented accumulation (br - br0 in {0,1,2})
        float s3[3] = {0.f, 0.f, 0.f};
        float n3[3] = {0.f, 0.f, 0.f};
        #pragma unroll
        for (int i = 0; i < 2; i++) {
            if (val[i]) {
                float d = sqrtf(fmaxf(a2[i] + fminf(mnA[i], mnB[i]), 1e-12f));
                float4 t = tg[bi[i] - b0][ni[i]];       // t = -0.5 * tg.xyz
                float dx = fmaf(0.5f, t.x, px[i]);
                float dy = fmaf(0.5f, t.y, py[i]);
                float dz = fmaf(0.5f, t.z, pz[i]);
                float ns = sqrtf(dx*dx + dy*dy + dz*dz);
                int slot = bri[i] - br0;
                if      (slot == 0) { s3[0] += d; n3[0] += ns; }
                else if (slot == 1) { s3[1] += d; n3[1] += ns; }
                else                { s3[2] += d; n3[2] += ns; }
            }
        }

        #pragma unroll
        for (int off = 16; off; off >>= 1) {
            #pragma unroll
            for (int c = 0; c < 3; c++) {
                s3[c] += __shfl_down_sync(0xffffffffu, s3[c], off);
                n3[c] += __shfl_down_sync(0xffffffffu, n3[c], off);
            }
        }
        if (lane == 0) {
            red6[wid][0]=s3[0]; red6[wid][1]=s3[1]; red6[wid][2]=s3[2];
            red6[wid][3]=n3[0]; red6[wid][4]=n3[1]; red6[wid][5]=n3[2];
        }
        __syncthreads();
        if (tid < 6) {
            float s = 0.f;
            #pragma unroll
            for (int k = 0; k < NWP; k++) s += red6[k][tid];
            if (tid < 3) g_symp[blk][tid]   = s;
            else         g_nsp[blk][tid-3]  = s;
        }
    } else {
        // ============ extras block: reg + huber ============
        float* anc = reinterpret_cast<float*>(tg);
        if (tid < NROT * 4) anc[tid] = rot_anchors[tid];
        __syncthreads();

        float regsum = 0.f;
        for (int i = tid; i < NBR; i += TPB) {
            int r = i % NROT;
            float q0 = pred_r[4*i], q1 = pred_r[4*i+1];
            float q2 = pred_r[4*i+2], q3 = pred_r[4*i+3];
            float mx = -3.4e38f, dg = 0.f;
            #pragma unroll 4
            for (int a = 0; a < NROT; a++) {
                float c = q0*anc[4*a] + q1*anc[4*a+1] + q2*anc[4*a+2] + q3*anc[4*a+3];
                mx = fmaxf(mx, c);
                if (a == r) dg = c;
            }
            float reg = mx - dg;
            regsum += (reg > 0.001f) ? reg : 0.f;
        }

        float tsum = 0.f;
        for (int i = tid; i < BS * NPTS; i += TPB) {
            int b  = i / NPTS;
            int ch = choose[i];
            const float* tb = target_t + (size_t)b * 3 * HW;
            float d0 = pred_t[3*i]   - tb[ch];
            float d1 = pred_t[3*i+1] - tb[HW + ch];
            float d2 = pred_t[3*i+2] - tb[2*HW + ch];
            float a0 = fabsf(d0), a1 = fabsf(d1), a2v = fabsf(d2);
            tsum += (a0 < 1.f) ? 0.5f*d0*d0 : (a0 - 0.5f);
            tsum += (a1 < 1.f) ? 0.5f*d1*d1 : (a1 - 0.5f);
            tsum += (a2v < 1.f) ? 0.5f*d2*d2 : (a2v - 0.5f);
        }

        #pragma unroll
        for (int off = 16; off; off >>= 1) {
            regsum += __shfl_down_sync(0xffffffffu, regsum, off);
            tsum   += __shfl_down_sync(0xffffffffu, tsum,   off);
        }
        if (lane == 0) { red6[wid][0] = regsum; red6[wid][1] = tsum; }
        __syncthreads();
        if (tid == 0) {
            float sa = 0.f, sb = 0.f;
            #pragma unroll
            for (int k = 0; k < NWP; k++) { sa += red6[k][0]; sb += red6[k][1]; }
            g_scal[0] = sa * (1.0f / NBR);
            g_scal[1] = sb * (1.0f / (BS*NPTS*3));
        }
    }

    // ============ grid completion: last block finalizes ============
    __threadfence();
    __syncthreads();
    if (tid == 0) {
        unsigned int ticket = atomicAdd(&g_cnt, 1u);
        s_last = (ticket == (unsigned)(GCH + 1) - 1u) ? 1 : 0;
    }
    __syncthreads();

    if (s_last) {
        float lr = 0.f;
        for (int i = tid; i < NBR; i += TPB) {
            const int b = i / NROT;
            int kA = block_of(i * NPTS);
            int kB = block_of(i * NPTS + NPTS - 1);
            float ssum = 0.f, nsum = 0.f;
            for (int k = kA; k <= kB; k++) {
                int slot = i - (g_start(k) / NPTS);
                if (slot >= 0 && slot < 3) {
                    ssum += g_symp[k][slot];
                    nsum += g_nsp[k][slot];
                }
            }
            float d = ((symmetric[b] != 0) ? ssum : nsum) * (1.0f / NPTS);
            float c = pred_c[i];
            lr += (d / (diameters[b] * c) + logf(c)) * (1.0f / NROT);
        }
        #pragma unroll
        for (int off = 16; off; off >>= 1)
            lr += __shfl_down_sync(0xffffffffu, lr, off);
        __syncthreads();
        if (lane == 0) red1[wid] = lr;
        __syncthreads();
        if (tid == 0) {
            float lrt = 0.f;
            #pragma unroll
            for (int k = 0; k < NWP; k++) lrt += red1[k];
            float lreg = g_scal[0];
            float lt   = g_scal[1];
            out[0] = lrt + 2.f * lreg + 5.f * lt;
            out[1] = lrt;
            out[2] = lreg;
            out[3] = lt;
            g_cnt = 0;   // reset for next graph replay
        }
    }
}

extern "C" void kernel_launch(void* const* d_in, const int* in_sizes, int n_in,
                              void* d_out, int out_size)
{
    fused_kernel<<<GCH + 1, TPB>>>(
        (const float*)d_in[0], (const float*)d_in[1], (const float*)d_in[2],
        (const float*)d_in[3], (const float*)d_in[4], (const float*)d_in[5],
        (const int*)d_in[6],   (const int*)d_in[7],   (const float*)d_in[8],
        (const float*)d_in[9], (float*)d_out);
}

// round 16
// speedup vs baseline: 1.0626x; 1.0626x over previous
#include <cuda_runtime.h>
#include <math.h>

#define BS    8
#define NROT  60
#define NPTS  500
#define NBR   (BS * NROT)     // 480
#define HW    6400            // 80*80
#define CHUNK 5               // targets batched per load group (500 = 5*100)
#define TPB   256
#define NW    (TPB / 32)

// Scratch (allocation-free: __device__ globals)
__device__ float g_sym[NBR];
__device__ float g_nonsym[NBR];
__device__ float g_scal[2];       // [0] = loss_reg, [1] = loss_t
__device__ unsigned int g_cnt;    // completion counter (reset by last block)

// ---------------------------------------------------------------------------
// Single fused kernel, grid = NBR + 1 blocks of 256 threads.
//  blocks 0..479 : chamfer for one (b, r); 2 pred points per thread
//  block  480    : reg loss + huber translation loss (runs concurrently)
//  last block to finish: finalize loss_r and combine into out[0..3]
// (R9 structure verbatim; only the prologue is vectorized.)
// ---------------------------------------------------------------------------
__global__ __launch_bounds__(TPB, 4) void fused_kernel(
    const float* __restrict__ pred_t,        // (8,500,3)
    const float* __restrict__ pred_r,        // (8,60,4)
    const float* __restrict__ pred_c,        // (8,60)
    const float* __restrict__ target_r,      // (8,1,500,3)
    const float* __restrict__ target_t,      // (8,3,80,80)
    const float* __restrict__ model_points,  // (8,1,500,3)
    const int*   __restrict__ choose,        // (8,500)
    const int*   __restrict__ symmetric,     // (8,) bool->int32
    const float* __restrict__ diameters,     // (8,)
    const float* __restrict__ rot_anchors,   // (60,4)
    float*       __restrict__ out)           // 4 floats
{
    __shared__ float4 tg[NPTS];    // per target: (-2tx, -2ty, -2tz, |t|^2)
    __shared__ float  redA[NW], redB[NW];
    __shared__ int    s_last;

    const int tid  = threadIdx.x;
    const int lane = tid & 31;
    const int wid  = tid >> 5;
    const int blk  = blockIdx.x;

    if (blk < NBR) {
        // ================= chamfer block =================
        const int b = blk / NROT;

        // Coalesced prologue: 1500 floats = 375 float4; threads 0..124 read
        // 3 each (LDG.128), producing 4 preprocessed targets apiece.
        const float4* tp4 = reinterpret_cast<const float4*>(target_r + (size_t)b * NPTS * 3);
        if (tid < 125) {
            float4 f0 = tp4[3*tid], f1 = tp4[3*tid+1], f2 = tp4[3*tid+2];
            tg[4*tid+0] = make_float4(-2.f*f0.x, -2.f*f0.y, -2.f*f0.z, f0.x*f0.x+f0.y*f0.y+f0.z*f0.z);
            tg[4*tid+1] = make_float4(-2.f*f0.w, -2.f*f1.x, -2.f*f1.y, f0.w*f0.w+f1.x*f1.x+f1.y*f1.y);
            tg[4*tid+2] = make_float4(-2.f*f1.z, -2.f*f1.w, -2.f*f2.x, f1.z*f1.z+f1.w*f1.w+f2.x*f2.x);
            tg[4*tid+3] = make_float4(-2.f*f2.y, -2.f*f2.z, -2.f*f2.w, f2.y*f2.y+f2.z*f2.z+f2.w*f2.w);
        }

        // Rotation matrix from (unnormalized) quaternion, as reference.
        const float* q = pred_r + (size_t)blk * 4;
        float w = q[0], x = q[1], y = q[2], z = q[3];
        float r00 = 1.f - 2.f*(y*y + z*z);
        float r01 = 2.f*x*y - 2.f*w*z;
        float r02 = 2.f*w*y + 2.f*x*z;
        float r10 = 2.f*x*y + 2.f*z*w;
        float r11 = 1.f - 2.f*(x*x + z*z);
        float r12 = -2.f*w*x + 2.f*y*z;
        float r20 = -2.f*w*y + 2.f*x*z;
        float r21 = 2.f*w*x + 2.f*y*z;
        float r22 = 1.f - 2.f*(x*x + y*y);

        __syncthreads();

        // 2 pred points per thread: n = tid, tid + 256
        const float* mpb = model_points + (size_t)b * NPTS * 3;
        float px[2], py[2], pz[2], a2[2];
        bool  val[2];
        #pragma unroll
        for (int i = 0; i < 2; i++) {
            int n = tid + TPB * i;
            val[i] = (n < NPTS);
            float mx = 0.f, my = 0.f, mz = 0.f;
            if (val[i]) { mx = mpb[3*n]; my = mpb[3*n+1]; mz = mpb[3*n+2]; }
            px[i] = r00*mx + r01*my + r02*mz;
            py[i] = r10*mx + r11*my + r12*mz;
            pz[i] = r20*mx + r21*my + r22*mz;
            a2[i] = px[i]*px[i] + py[i]*py[i] + pz[i]*pz[i];
        }

        const float INF = 3.4e38f;
        // Two min accumulators per point (chunk parity) to break FMNMX chains.
        float mnA[2] = {INF, INF};
        float mnB[2] = {INF, INF};

        // Scalar inner loop: per target 1 LDS.128 + 2x(3 FFMA + 1 FMNMX).
        for (int j0 = 0; j0 < NPTS; j0 += CHUNK) {
            float4 T[CHUNK];
            #pragma unroll
            for (int k = 0; k < CHUNK; k++) T[k] = tg[j0 + k];
            #pragma unroll
            for (int k = 0; k < CHUNK; k++) {
                #pragma unroll
                for (int i = 0; i < 2; i++) {
                    float s = fmaf(px[i], T[k].x,
                              fmaf(py[i], T[k].y,
                              fmaf(pz[i], T[k].z, T[k].w)));
                    if (k & 1) mnB[i] = fminf(mnB[i], s);
                    else       mnA[i] = fminf(mnA[i], s);
                }
            }
        }

        float symsum = 0.f, nssum = 0.f;
        #pragma unroll
        for (int i = 0; i < 2; i++) {
            if (val[i]) {
                float m = fminf(mnA[i], mnB[i]);
                symsum += sqrtf(fmaxf(a2[i] + m, 1e-12f));
                int n = tid + TPB * i;
                float4 t = tg[n];          // recover t: t = -0.5 * tg.xyz
                float dx = fmaf(0.5f, t.x, px[i]);
                float dy = fmaf(0.5f, t.y, py[i]);
                float dz = fmaf(0.5f, t.z, pz[i]);
                nssum += sqrtf(dx*dx + dy*dy + dz*dz);
            }
        }

        #pragma unroll
        for (int off = 16; off; off >>= 1) {
            symsum += __shfl_down_sync(0xffffffffu, symsum, off);
            nssum  += __shfl_down_sync(0xffffffffu, nssum,  off);
        }
        if (lane == 0) { redA[wid] = symsum; redB[wid] = nssum; }
        __syncthreads();
        if (tid == 0) {
            float sa = 0.f, sb = 0.f;
            #pragma unroll
            for (int k = 0; k < NW; k++) { sa += redA[k]; sb += redB[k]; }
            g_sym[blk]    = sa * (1.0f / NPTS);
            g_nonsym[blk] = sb * (1.0f / NPTS);
        }
    } else {
        // ================= reg + huber block =================
        float* anc = reinterpret_cast<float*>(tg);  // 240 floats
        for (int i = tid; i < NROT * 4; i += TPB) anc[i] = rot_anchors[i];
        __syncthreads();

        float regsum = 0.f;
        for (int i = tid; i < NBR; i += TPB) {
            int r = i % NROT;
            float q0 = pred_r[4*i], q1 = pred_r[4*i+1];
            float q2 = pred_r[4*i+2], q3 = pred_r[4*i+3];
            float mx = -3.4e38f, dg = 0.f;
            #pragma unroll 4
            for (int a = 0; a < NROT; a++) {
                float c = q0*anc[4*a] + q1*anc[4*a+1] + q2*anc[4*a+2] + q3*anc[4*a+3];
                mx = fmaxf(mx, c);
                if (a == r) dg = c;
            }
            float reg = mx - dg;
            regsum += (reg > 0.001f) ? reg : 0.f;
        }

        float tsum = 0.f;
        for (int i = tid; i < BS * NPTS; i += TPB) {
            int b  = i / NPTS;
            int ch = choose[i];
            const float* tb = target_t + (size_t)b * 3 * HW;
            float tv0 = tb[ch], tv1 = tb[HW + ch], tv2 = tb[2*HW + ch];
            float p0 = pred_t[3*i], p1 = pred_t[3*i+1], p2 = pred_t[3*i+2];
            float d0 = p0 - tv0, d1 = p1 - tv1, d2 = p2 - tv2;
            float a0 = fabsf(d0), a1 = fabsf(d1), a2v = fabsf(d2);
            tsum += (a0 < 1.f) ? 0.5f*d0*d0 : (a0 - 0.5f);
            tsum += (a1 < 1.f) ? 0.5f*d1*d1 : (a1 - 0.5f);
            tsum += (a2v < 1.f) ? 0.5f*d2*d2 : (a2v - 0.5f);
        }

        #pragma unroll
        for (int off = 16; off; off >>= 1) {
            regsum += __shfl_down_sync(0xffffffffu, regsum, off);
            tsum   += __shfl_down_sync(0xffffffffu, tsum,   off);
        }
        if (lane == 0) { redA[wid] = regsum; redB[wid] = tsum; }
        __syncthreads();
        if (tid == 0) {
            float sa = 0.f, sb = 0.f;
            #pragma unroll
            for (int k = 0; k < NW; k++) { sa += redA[k]; sb += redB[k]; }
            g_scal[0] = sa * (1.0f / NBR);
            g_scal[1] = sb * (1.0f / (BS*NPTS*3));
        }
    }

    // ================= grid-completion: last block finalizes =================
    __threadfence();
    if (tid == 0) {
        unsigned int ticket = atomicAdd(&g_cnt, 1u);
        s_last = (ticket == (unsigned)(NBR + 1) - 1u) ? 1 : 0;
    }
    __syncthreads();

    if (s_last) {
        float lr = 0.f;
        for (int i = tid; i < NBR; i += TPB) {
            int b = i / NROT;
            float d = (symmetric[b] != 0) ? g_sym[i] : g_nonsym[i];
            float c = pred_c[i];
            lr += (d / (diameters[b] * c) + logf(c)) * (1.0f / NROT);
        }
        #pragma unroll
        for (int off = 16; off; off >>= 1)
            lr += __shfl_down_sync(0xffffffffu, lr, off);
        if (lane == 0) redA[wid] = lr;
        __syncthreads();
        if (tid == 0) {
            float lrt = 0.f;
            #pragma unroll
            for (int k = 0; k < NW; k++) lrt += redA[k];
            float lreg = g_scal[0];
            float lt   = g_scal[1];
            out[0] = lrt + 2.f * lreg + 5.f * lt;
            out[1] = lrt;
            out[2] = lreg;
            out[3] = lt;
            g_cnt = 0;   // reset for next graph replay
        }
    }
}

// ---------------------------------------------------------------------------
// Launch. Input order: pred_t, pred_r, pred_c, target_r, target_t,
//                      model_points, choose, symmetric, diameters, rot_anchors
// ---------------------------------------------------------------------------
extern "C" void kernel_launch(void* const* d_in, const int* in_sizes, int n_in,
                              void* d_out, int out_size)
{
    fused_kernel<<<NBR + 1, TPB>>>(
        (const float*)d_in[0], (const float*)d_in[1], (const float*)d_in[2],
        (const float*)d_in[3], (const float*)d_in[4], (const float*)d_in[5],
        (const int*)d_in[6],   (const int*)d_in[7],   (const float*)d_in[8],
        (const float*)d_in[9], (float*)d_out);
}